// round 14
// baseline (speedup 1.0000x reference)
#include <cuda_runtime.h>
#include <cuda_fp16.h>
#include <cstdint>
#include <stdint.h>

// Problem constants (fixed shapes)
#define NN 100000
#define EE 1600000
#define SCAN_CHUNK 1024
#define SCAN_BLOCKS ((NN + SCAN_CHUNK - 1) / SCAN_CHUNK)   // 98
#define NSPLIT 50048                                       // 391 * 128

// ---------------- device scratch (static globals; no runtime alloc) -------------
// Invariants re-established every call: g_cnt zeroed by k_scan_fused after use;
// g_arrive zeroed by k_fill. Both are zero-init BSS on first call.
__device__ int    g_cnt[NN];
__device__ int    g_off[NN];         // after fill: g_off[d] = end of segment d
__device__ int    g_part[SCAN_BLOCKS];
__device__ int    g_arrive;
__device__ float  g_dinv[NN];
__device__ int    g_csr[EE];
__device__ __half g_h  [NN * 128];   // dinv * (x @ W1)      (pre-scaled rows)
__device__ __half g_a  [NN * 128];   // relu(Ahat@h+b1)
__device__ __half g_t2 [NN * 64];    // dinv * (g_a @ W2)    (pre-scaled rows)
__device__ __half g_w1t[128 * 128];  // W1^T  [n][k] fp16 (k contiguous)
__device__ __half g_w2t[64 * 128];   // W2^T  [n][k] fp16

// ---------------- weight prep: transpose + fp16 convert -------------------------
__global__ void k_wprep(const float* __restrict__ W1, const float* __restrict__ W2) {
    int i = blockIdx.x * blockDim.x + threadIdx.x;
    if (i < 128 * 128) {
        int n = i >> 7, k = i & 127;
        g_w1t[i] = __float2half(W1[k * 128 + n]);
    }
    if (i < 64 * 128) {
        int n = i >> 7, k = i & 127;
        g_w2t[i] = __float2half(W2[k * 64 + n]);
    }
}

// ---------------- degree / CSR construction ------------------------------------
// edge_index is INT32: layout [2, E] -> src = ei[e], dst = ei[E+e]
__global__ void k_count(const int* __restrict__ ei) {
    int i = blockIdx.x * blockDim.x + threadIdx.x;
    if (i < EE / 4) {
        int4 d = ((const int4*)(ei + EE))[i];
        atomicAdd(&g_cnt[d.x], 1);
        atomicAdd(&g_cnt[d.y], 1);
        atomicAdd(&g_cnt[d.z], 1);
        atomicAdd(&g_cnt[d.w], 1);
    }
}

// Single-kernel exclusive scan (single wave: 98 blocks co-resident).
// Also computes dinv and re-zeroes g_cnt.
__global__ void k_scan_fused() {
    __shared__ int warpsum[32];
    __shared__ int base_s;
    const int tid  = threadIdx.x;
    const int lane = tid & 31;
    const int wid  = tid >> 5;
    const int bid  = blockIdx.x;
    const int i = bid * SCAN_CHUNK + tid;

    int v = 0;
    if (i < NN) {
        v = g_cnt[i];
        g_cnt[i] = 0;                              // restore invariant
        g_dinv[i] = rsqrtf((float)(v + 1));        // +1 self-loop
    }
    int s = v;
    #pragma unroll
    for (int d = 1; d < 32; d <<= 1) {
        int t = __shfl_up_sync(0xffffffffu, s, d);
        if (lane >= d) s += t;
    }
    if (lane == 31) warpsum[wid] = s;
    __syncthreads();
    if (wid == 0) {
        int ws = warpsum[lane];
        #pragma unroll
        for (int d = 1; d < 32; d <<= 1) {
            int t = __shfl_up_sync(0xffffffffu, ws, d);
            if (lane >= d) ws += t;
        }
        warpsum[lane] = ws;
    }
    __syncthreads();
    int block_excl = (wid == 0) ? 0 : warpsum[wid - 1];
    int excl = s + block_excl - v;                 // exclusive within block
    int btotal = warpsum[31];

    // publish block total, then wait for all blocks (co-resident -> safe)
    if (tid == 0) {
        g_part[bid] = btotal;
        __threadfence();
        atomicAdd(&g_arrive, 1);
        while (atomicAdd(&g_arrive, 0) < SCAN_BLOCKS) { }
    }
    __syncthreads();

    // warp 0 sums predecessors' totals (atomic reads -> L2-coherent)
    if (tid < 32) {
        int acc = 0;
        for (int j = tid; j < bid; j += 32) acc += atomicAdd(&g_part[j], 0);
        #pragma unroll
        for (int d = 16; d; d >>= 1) acc += __shfl_down_sync(0xffffffffu, acc, d);
        if (tid == 0) base_s = acc;
    }
    __syncthreads();
    if (i < NN) g_off[i] = excl + base_s;
}

// fill bumps g_off directly; resets g_arrive for the next call
__global__ void k_fill(const int* __restrict__ ei) {
    int i = blockIdx.x * blockDim.x + threadIdx.x;
    if (i == 0) g_arrive = 0;
    if (i < EE / 4) {
        int4 s = ((const int4*)ei)[i];
        int4 d = ((const int4*)(ei + EE))[i];
        g_csr[atomicAdd(&g_off[d.x], 1)] = s.x;
        g_csr[atomicAdd(&g_off[d.y], 1)] = s.y;
        g_csr[atomicAdd(&g_off[d.z], 1)] = s.z;
        g_csr[atomicAdd(&g_off[d.w], 1)] = s.w;
    }
}

// ---------------- tensor-core helpers -------------------------------------------
__device__ __forceinline__ unsigned smem_u32(const void* p) {
    return (unsigned)__cvta_generic_to_shared(p);
}
__device__ __forceinline__ void ldsm_x4(unsigned& r0, unsigned& r1, unsigned& r2,
                                        unsigned& r3, unsigned addr) {
    asm volatile("ldmatrix.sync.aligned.m8n8.x4.shared.b16 {%0,%1,%2,%3}, [%4];"
                 : "=r"(r0), "=r"(r1), "=r"(r2), "=r"(r3) : "r"(addr));
}
__device__ __forceinline__ void ldsm_x2(unsigned& r0, unsigned& r1, unsigned addr) {
    asm volatile("ldmatrix.sync.aligned.m8n8.x2.shared.b16 {%0,%1}, [%2];"
                 : "=r"(r0), "=r"(r1) : "r"(addr));
}
__device__ __forceinline__ void mma16816(float& c0, float& c1, float& c2, float& c3,
                                         unsigned a0, unsigned a1, unsigned a2, unsigned a3,
                                         unsigned b0, unsigned b1) {
    asm volatile(
        "mma.sync.aligned.m16n8k16.row.col.f32.f16.f16.f32 "
        "{%0,%1,%2,%3}, {%4,%5,%6,%7}, {%8,%9}, {%0,%1,%2,%3};"
        : "+f"(c0), "+f"(c1), "+f"(c2), "+f"(c3)
        : "r"(a0), "r"(a1), "r"(a2), "r"(a3), "r"(b0), "r"(b1));
}

// ---------------- HMMA GEMM: C[m] = dinv[m] * (A[m] @ W), fp16 out ---------------
// Block tile 128 x BN, BK=32, 256 threads (8 warps). rowOff selects row range.
// MODE 0: A = x (fp32 arg) -> g_h    (BN=128, WM=64, WN=32)
// MODE 1: A = g_a (fp16)   -> g_t2   (BN=64,  WM=32, WN=32)
#define SPITCH 40   // halves per smem row (conflict-free under ldmatrix)

template <int BN, int WM, int WN, int MODE>
__global__ __launch_bounds__(256) void hgemm(const float* __restrict__ Xf, int rowOff) {
    constexpr int MF = WM / 16;
    constexpr int NF = WN / 8;
    constexpr int NWN = BN / WN;

    __shared__ __half sA[128 * SPITCH];
    __shared__ __half sB[BN * SPITCH];

    const int t    = threadIdx.x;
    const int lane = t & 31;
    const int wid  = t >> 5;
    const int m_w  = (wid / NWN) * WM;
    const int n_w  = (wid % NWN) * WN;
    const int rowB = rowOff + blockIdx.x * 128;

    __half* __restrict__ Ch = (MODE == 0) ? g_h : g_t2;
    const __half* __restrict__ Bt = (MODE == 0) ? g_w1t : g_w2t;
    const __half* __restrict__ Ah = g_a;

    float acc[MF][NF][4];
    #pragma unroll
    for (int i = 0; i < MF; ++i)
        #pragma unroll
        for (int j = 0; j < NF; ++j)
            #pragma unroll
            for (int q = 0; q < 4; ++q) acc[i][j][q] = 0.f;

    // loader indices: 2 threads per row, 16 halves each
    const int arow = t >> 1;
    const int asub = t & 1;

    #pragma unroll 1
    for (int kc = 0; kc < 4; ++kc) {
        const int k0 = kc * 32;
        // ---- load A tile: 128 rows x 32 halves
        {
            int gr = rowB + arow;
            uint4 u0, u1;
            if (MODE == 0) {
                float4 f0, f1, f2, f3;
                if (gr < NN) {
                    const float4* Xr = (const float4*)Xf + (size_t)gr * 32 + kc * 8 + asub * 4;
                    f0 = Xr[0]; f1 = Xr[1]; f2 = Xr[2]; f3 = Xr[3];
                } else {
                    f0 = f1 = f2 = f3 = make_float4(0.f, 0.f, 0.f, 0.f);
                }
                __half2 h0 = __floats2half2_rn(f0.x, f0.y), h1 = __floats2half2_rn(f0.z, f0.w);
                __half2 h2 = __floats2half2_rn(f1.x, f1.y), h3 = __floats2half2_rn(f1.z, f1.w);
                __half2 h4 = __floats2half2_rn(f2.x, f2.y), h5 = __floats2half2_rn(f2.z, f2.w);
                __half2 h6 = __floats2half2_rn(f3.x, f3.y), h7 = __floats2half2_rn(f3.z, f3.w);
                u0 = make_uint4(*(unsigned*)&h0, *(unsigned*)&h1, *(unsigned*)&h2, *(unsigned*)&h3);
                u1 = make_uint4(*(unsigned*)&h4, *(unsigned*)&h5, *(unsigned*)&h6, *(unsigned*)&h7);
            } else {
                if (gr < NN) {
                    const uint4* Ar = (const uint4*)(Ah + (size_t)gr * 128 + k0 + asub * 16);
                    u0 = Ar[0]; u1 = Ar[1];
                } else {
                    u0 = make_uint4(0u, 0u, 0u, 0u);
                    u1 = make_uint4(0u, 0u, 0u, 0u);
                }
            }
            uint4* dst = (uint4*)&sA[arow * SPITCH + asub * 16];
            dst[0] = u0; dst[1] = u1;
        }
        // ---- load B tile: BN rows x 32 halves (from pre-transposed fp16 weights)
        if (BN == 128 || t < 128) {
            int n = arow;            // for BN=64 only t<128 -> n<64
            const uint4* Br = (const uint4*)(Bt + (size_t)n * 128 + k0 + asub * 16);
            uint4* dst = (uint4*)&sB[n * SPITCH + asub * 16];
            dst[0] = Br[0]; dst[1] = Br[1];
        }
        __syncthreads();

        // ---- compute: 2 k16 steps
        #pragma unroll
        for (int ks = 0; ks < 2; ++ks) {
            unsigned af[MF][4];
            #pragma unroll
            for (int mf = 0; mf < MF; ++mf) {
                int r = m_w + mf * 16 + (lane & 15);
                int c = ks * 16 + ((lane >> 4) << 3);
                ldsm_x4(af[mf][0], af[mf][1], af[mf][2], af[mf][3],
                        smem_u32(&sA[r * SPITCH + c]));
            }
            unsigned bf[NF][2];
            #pragma unroll
            for (int nf = 0; nf < NF; ++nf) {
                int r = n_w + nf * 8 + (lane & 7);
                int c = ks * 16 + ((lane >> 3) & 1) * 8;
                ldsm_x2(bf[nf][0], bf[nf][1], smem_u32(&sB[r * SPITCH + c]));
            }
            #pragma unroll
            for (int mf = 0; mf < MF; ++mf)
                #pragma unroll
                for (int nf = 0; nf < NF; ++nf)
                    mma16816(acc[mf][nf][0], acc[mf][nf][1], acc[mf][nf][2], acc[mf][nf][3],
                             af[mf][0], af[mf][1], af[mf][2], af[mf][3],
                             bf[nf][0], bf[nf][1]);
        }
        __syncthreads();
    }

    // ---- epilogue: scale row m by dinv[m], store fp16
    #pragma unroll
    for (int mf = 0; mf < MF; ++mf) {
        int m0 = rowB + m_w + mf * 16 + (lane >> 2);
        float d0 = (m0     < NN) ? g_dinv[m0]     : 0.f;
        float d1 = (m0 + 8 < NN) ? g_dinv[m0 + 8] : 0.f;
        #pragma unroll
        for (int nf = 0; nf < NF; ++nf) {
            int n = n_w + nf * 8 + (lane & 3) * 2;
            if (m0 < NN) {
                __half2 p = __floats2half2_rn(acc[mf][nf][0] * d0, acc[mf][nf][1] * d0);
                *(__half2*)(Ch + (size_t)m0 * BN + n) = p;
            }
            if (m0 + 8 < NN) {
                __half2 p = __floats2half2_rn(acc[mf][nf][2] * d1, acc[mf][nf][3] * d1);
                *(__half2*)(Ch + (size_t)(m0 + 8) * BN + n) = p;
            }
        }
    }
}

// ---------------- gather SpMM (layer 1): 128 cols fp16, one warp per node ------
// segment of node gw = [gw? g_off[gw-1] : 0, g_off[gw])  (post-fill semantics)
__global__ void spmm1(const float* __restrict__ b1, int nodeBase) {
    int gw   = nodeBase + ((blockIdx.x * blockDim.x + threadIdx.x) >> 5);
    int lane = threadIdx.x & 31;
    if (gw >= NN) return;
    const __half* __restrict__ H = g_h;
    float dv = g_dinv[gw];

    uint2 h0 = *(const uint2*)(H + (size_t)gw * 128 + lane * 4);
    float2 p0 = __half22float2(*(__half2*)&h0.x);
    float2 p1 = __half22float2(*(__half2*)&h0.y);
    float a0 = p0.x, a1 = p0.y, a2 = p1.x, a3 = p1.y;

    int e  = (gw == 0) ? 0 : g_off[gw - 1];
    int e1 = g_off[gw];
    for (; e + 4 <= e1; e += 4) {
        int s0 = g_csr[e];
        int s1 = g_csr[e + 1];
        int s2 = g_csr[e + 2];
        int s3 = g_csr[e + 3];
        uint2 u0 = *(const uint2*)(H + (size_t)s0 * 128 + lane * 4);
        uint2 u1 = *(const uint2*)(H + (size_t)s1 * 128 + lane * 4);
        uint2 u2 = *(const uint2*)(H + (size_t)s2 * 128 + lane * 4);
        uint2 u3 = *(const uint2*)(H + (size_t)s3 * 128 + lane * 4);
        float2 q0 = __half22float2(*(__half2*)&u0.x), q1 = __half22float2(*(__half2*)&u0.y);
        float2 r0 = __half22float2(*(__half2*)&u1.x), r1 = __half22float2(*(__half2*)&u1.y);
        float2 w0 = __half22float2(*(__half2*)&u2.x), w1 = __half22float2(*(__half2*)&u2.y);
        float2 z0 = __half22float2(*(__half2*)&u3.x), z1 = __half22float2(*(__half2*)&u3.y);
        a0 += (q0.x + r0.x) + (w0.x + z0.x);
        a1 += (q0.y + r0.y) + (w0.y + z0.y);
        a2 += (q1.x + r1.x) + (w1.x + z1.x);
        a3 += (q1.y + r1.y) + (w1.y + z1.y);
    }
    for (; e < e1; ++e) {
        int s = g_csr[e];
        uint2 u = *(const uint2*)(H + (size_t)s * 128 + lane * 4);
        float2 q0 = __half22float2(*(__half2*)&u.x);
        float2 q1 = __half22float2(*(__half2*)&u.y);
        a0 += q0.x; a1 += q0.y; a2 += q1.x; a3 += q1.y;
    }
    float4 b = ((const float4*)b1)[lane];
    a0 = fmaxf(a0 * dv + b.x, 0.f);
    a1 = fmaxf(a1 * dv + b.y, 0.f);
    a2 = fmaxf(a2 * dv + b.z, 0.f);
    a3 = fmaxf(a3 * dv + b.w, 0.f);
    uint2 o;
    *(__half2*)&o.x = __floats2half2_rn(a0, a1);
    *(__half2*)&o.y = __floats2half2_rn(a2, a3);
    *(uint2*)(g_a + (size_t)gw * 128 + lane * 4) = o;
}

// ---------------- gather SpMM (layer 2): 64 cols fp16 in, fp32 out -------------
__global__ void spmm2(const float* __restrict__ b2, float* __restrict__ O) {
    int gw   = (blockIdx.x * blockDim.x + threadIdx.x) >> 5;
    int lane = threadIdx.x & 31;
    if (gw >= NN) return;
    const __half* __restrict__ T = g_t2;
    float dv = g_dinv[gw];

    float2 t0 = __half22float2(*(const __half2*)(T + (size_t)gw * 64 + lane * 2));
    float a0 = t0.x, a1 = t0.y;

    int e  = (gw == 0) ? 0 : g_off[gw - 1];
    int e1 = g_off[gw];
    for (; e + 4 <= e1; e += 4) {
        int s0 = g_csr[e];
        int s1 = g_csr[e + 1];
        int s2 = g_csr[e + 2];
        int s3 = g_csr[e + 3];
        float2 v0 = __half22float2(*(const __half2*)(T + (size_t)s0 * 64 + lane * 2));
        float2 v1 = __half22float2(*(const __half2*)(T + (size_t)s1 * 64 + lane * 2));
        float2 v2 = __half22float2(*(const __half2*)(T + (size_t)s2 * 64 + lane * 2));
        float2 v3 = __half22float2(*(const __half2*)(T + (size_t)s3 * 64 + lane * 2));
        a0 += (v0.x + v1.x) + (v2.x + v3.x);
        a1 += (v0.y + v1.y) + (v2.y + v3.y);
    }
    for (; e < e1; ++e) {
        int s = g_csr[e];
        float2 v = __half22float2(*(const __half2*)(T + (size_t)s * 64 + lane * 2));
        a0 += v.x;
        a1 += v.y;
    }
    float2 b = ((const float2*)b2)[lane];
    ((float2*)O)[(size_t)gw * 32 + lane] = make_float2(a0 * dv + b.x, a1 * dv + b.y);
}

// ---------------- launch: fork CSR build; overlap hgemm2 half with spmm1 half ----
extern "C" void kernel_launch(void* const* d_in, const int* in_sizes, int n_in,
                              void* d_out, int out_size) {
    const float* x  = (const float*)d_in[0];
    const int*   ei = (const int*)d_in[1];     // int32 [2, E]
    const float* W1 = (const float*)d_in[2];
    const float* b1 = (const float*)d_in[3];
    const float* W2 = (const float*)d_in[4];
    const float* b2 = (const float*)d_in[5];
    float*       out = (float*)d_out;

    cudaStream_t s1;
    cudaStreamCreateWithFlags(&s1, cudaStreamNonBlocking);
    cudaEvent_t evFork, evDinv, evFill, evS1a, evG2a;
    cudaEventCreateWithFlags(&evFork, cudaEventDisableTiming);
    cudaEventCreateWithFlags(&evDinv, cudaEventDisableTiming);
    cudaEventCreateWithFlags(&evFill, cudaEventDisableTiming);
    cudaEventCreateWithFlags(&evS1a, cudaEventDisableTiming);
    cudaEventCreateWithFlags(&evG2a, cudaEventDisableTiming);

    const int TB = 256;

    // fork: s1 branches off the (captured) main stream
    cudaEventRecord(evFork, 0);
    cudaStreamWaitEvent(s1, evFork, 0);

    // ---- CSR build chain on s1
    k_count     <<<(EE / 4 + TB - 1) / TB, TB, 0, s1>>>(ei);
    k_scan_fused<<<SCAN_BLOCKS, SCAN_CHUNK, 0, s1>>>();
    cudaEventRecord(evDinv, s1);                 // dinv ready
    k_fill      <<<(EE / 4 + TB - 1) / TB, TB, 0, s1>>>(ei);
    cudaEventRecord(evFill, s1);                 // CSR ready

    // ---- main stream: weight prep concurrent with CSR build
    k_wprep<<<64, 256>>>(W1, W2);

    // hgemm1 (needs dinv only)
    cudaStreamWaitEvent(0, evDinv, 0);
    hgemm<128, 64, 32, 0><<<(NN + 127) / 128, 256>>>(x, 0);

    // spmm1 first half (needs full CSR)
    cudaStreamWaitEvent(0, evFill, 0);
    spmm1<<<(NSPLIT * 32) / TB, TB>>>(b1, 0);
    cudaEventRecord(evS1a, 0);

    // hgemm2 first half on s1, overlapped with spmm1 second half on main
    cudaStreamWaitEvent(s1, evS1a, 0);
    hgemm<64, 32, 32, 1><<<NSPLIT / 128, 256, 0, s1>>>(x /*unused*/, 0);
    cudaEventRecord(evG2a, s1);

    spmm1<<<((NN - NSPLIT) * 32 + TB - 1) / TB, TB>>>(b1, NSPLIT);
    hgemm<64, 32, 32, 1><<<(NN - NSPLIT + 127) / 128, 256>>>(x /*unused*/, NSPLIT);

    // spmm2 needs both hgemm2 halves
    cudaStreamWaitEvent(0, evG2a, 0);
    spmm2<<<(NN * 32 + TB - 1) / TB, TB>>>(b2, out);
}

// round 15
// speedup vs baseline: 1.0175x; 1.0175x over previous
#include <cuda_runtime.h>
#include <cuda_fp16.h>
#include <cstdint>
#include <stdint.h>

// Problem constants (fixed shapes)
#define NN 100000
#define EE 1600000
#define SCAN_CHUNK 1024
#define SCAN_BLOCKS ((NN + SCAN_CHUNK - 1) / SCAN_CHUNK)   // 98

// ---------------- device scratch (static globals; no runtime alloc) -------------
// Invariants re-established every call: g_cnt zeroed by k_scan_fused after use;
// g_arrive zeroed by k_fill. Both are zero-init BSS on first call.
__device__ int    g_cnt[NN];
__device__ int    g_off[NN];         // after fill: g_off[d] = end of segment d
__device__ int    g_part[SCAN_BLOCKS];
__device__ int    g_arrive;
__device__ float  g_dinv[NN];
__device__ int    g_csr[EE];
__device__ __half g_h  [NN * 128];   // dinv * (x @ W1)      (pre-scaled rows)
__device__ __half g_a  [NN * 128];   // relu(Ahat@h+b1)
__device__ __half g_t2 [NN * 64];    // dinv * (g_a @ W2)    (pre-scaled rows)
__device__ __half g_w1t[128 * 128];  // W1^T  [n][k] fp16 (k contiguous)
__device__ __half g_w2t[64 * 128];   // W2^T  [n][k] fp16

// ---------------- weight prep: transpose + fp16 convert -------------------------
__global__ void k_wprep(const float* __restrict__ W1, const float* __restrict__ W2) {
    int i = blockIdx.x * blockDim.x + threadIdx.x;
    if (i < 128 * 128) {
        int n = i >> 7, k = i & 127;
        g_w1t[i] = __float2half(W1[k * 128 + n]);
    }
    if (i < 64 * 128) {
        int n = i >> 7, k = i & 127;
        g_w2t[i] = __float2half(W2[k * 64 + n]);
    }
}

// ---------------- degree / CSR construction ------------------------------------
// edge_index is INT32: layout [2, E] -> src = ei[e], dst = ei[E+e]
__global__ void k_count(const int* __restrict__ ei) {
    int i = blockIdx.x * blockDim.x + threadIdx.x;
    if (i < EE / 4) {
        int4 d = ((const int4*)(ei + EE))[i];
        atomicAdd(&g_cnt[d.x], 1);
        atomicAdd(&g_cnt[d.y], 1);
        atomicAdd(&g_cnt[d.z], 1);
        atomicAdd(&g_cnt[d.w], 1);
    }
}

// Single-kernel exclusive scan (single wave: 98 blocks co-resident).
// Also computes dinv and re-zeroes g_cnt.
__global__ void k_scan_fused() {
    __shared__ int warpsum[32];
    __shared__ int base_s;
    const int tid  = threadIdx.x;
    const int lane = tid & 31;
    const int wid  = tid >> 5;
    const int bid  = blockIdx.x;
    const int i = bid * SCAN_CHUNK + tid;

    int v = 0;
    if (i < NN) {
        v = g_cnt[i];
        g_cnt[i] = 0;                              // restore invariant
        g_dinv[i] = rsqrtf((float)(v + 1));        // +1 self-loop
    }
    int s = v;
    #pragma unroll
    for (int d = 1; d < 32; d <<= 1) {
        int t = __shfl_up_sync(0xffffffffu, s, d);
        if (lane >= d) s += t;
    }
    if (lane == 31) warpsum[wid] = s;
    __syncthreads();
    if (wid == 0) {
        int ws = warpsum[lane];
        #pragma unroll
        for (int d = 1; d < 32; d <<= 1) {
            int t = __shfl_up_sync(0xffffffffu, ws, d);
            if (lane >= d) ws += t;
        }
        warpsum[lane] = ws;
    }
    __syncthreads();
    int block_excl = (wid == 0) ? 0 : warpsum[wid - 1];
    int excl = s + block_excl - v;                 // exclusive within block
    int btotal = warpsum[31];

    // publish block total, then wait for all blocks (co-resident -> safe)
    if (tid == 0) {
        g_part[bid] = btotal;
        __threadfence();
        atomicAdd(&g_arrive, 1);
        while (atomicAdd(&g_arrive, 0) < SCAN_BLOCKS) { }
    }
    __syncthreads();

    // warp 0 sums predecessors' totals (atomic reads -> L2-coherent)
    if (tid < 32) {
        int acc = 0;
        for (int j = tid; j < bid; j += 32) acc += atomicAdd(&g_part[j], 0);
        #pragma unroll
        for (int d = 16; d; d >>= 1) acc += __shfl_down_sync(0xffffffffu, acc, d);
        if (tid == 0) base_s = acc;
    }
    __syncthreads();
    if (i < NN) g_off[i] = excl + base_s;
}

// fill bumps g_off directly; 8 edges per thread (2x int4) for deeper atomic MLP;
// resets g_arrive for the next call
__global__ void k_fill(const int* __restrict__ ei) {
    int i = blockIdx.x * blockDim.x + threadIdx.x;
    if (i == 0) g_arrive = 0;
    if (i < EE / 8) {
        int4 s0 = ((const int4*)ei)[2 * i];
        int4 s1 = ((const int4*)ei)[2 * i + 1];
        int4 d0 = ((const int4*)(ei + EE))[2 * i];
        int4 d1 = ((const int4*)(ei + EE))[2 * i + 1];
        int p0 = atomicAdd(&g_off[d0.x], 1);
        int p1 = atomicAdd(&g_off[d0.y], 1);
        int p2 = atomicAdd(&g_off[d0.z], 1);
        int p3 = atomicAdd(&g_off[d0.w], 1);
        int p4 = atomicAdd(&g_off[d1.x], 1);
        int p5 = atomicAdd(&g_off[d1.y], 1);
        int p6 = atomicAdd(&g_off[d1.z], 1);
        int p7 = atomicAdd(&g_off[d1.w], 1);
        g_csr[p0] = s0.x;
        g_csr[p1] = s0.y;
        g_csr[p2] = s0.z;
        g_csr[p3] = s0.w;
        g_csr[p4] = s1.x;
        g_csr[p5] = s1.y;
        g_csr[p6] = s1.z;
        g_csr[p7] = s1.w;
    }
}

// ---------------- tensor-core helpers -------------------------------------------
__device__ __forceinline__ unsigned smem_u32(const void* p) {
    return (unsigned)__cvta_generic_to_shared(p);
}
__device__ __forceinline__ void ldsm_x4(unsigned& r0, unsigned& r1, unsigned& r2,
                                        unsigned& r3, unsigned addr) {
    asm volatile("ldmatrix.sync.aligned.m8n8.x4.shared.b16 {%0,%1,%2,%3}, [%4];"
                 : "=r"(r0), "=r"(r1), "=r"(r2), "=r"(r3) : "r"(addr));
}
__device__ __forceinline__ void ldsm_x2(unsigned& r0, unsigned& r1, unsigned addr) {
    asm volatile("ldmatrix.sync.aligned.m8n8.x2.shared.b16 {%0,%1}, [%2];"
                 : "=r"(r0), "=r"(r1) : "r"(addr));
}
__device__ __forceinline__ void mma16816(float& c0, float& c1, float& c2, float& c3,
                                         unsigned a0, unsigned a1, unsigned a2, unsigned a3,
                                         unsigned b0, unsigned b1) {
    asm volatile(
        "mma.sync.aligned.m16n8k16.row.col.f32.f16.f16.f32 "
        "{%0,%1,%2,%3}, {%4,%5,%6,%7}, {%8,%9}, {%0,%1,%2,%3};"
        : "+f"(c0), "+f"(c1), "+f"(c2), "+f"(c3)
        : "r"(a0), "r"(a1), "r"(a2), "r"(a3), "r"(b0), "r"(b1));
}

// ---------------- HMMA GEMM: C[m] = dinv[m] * (A[m] @ W), fp16 out ---------------
// Block tile 128 x BN, BK=32, 256 threads (8 warps).
// MODE 0: A = x (fp32 arg) -> g_h    (BN=128, WM=64, WN=32)
// MODE 1: A = g_a (fp16)   -> g_t2   (BN=64,  WM=32, WN=32)
#define SPITCH 40   // halves per smem row (conflict-free under ldmatrix)

template <int BN, int WM, int WN, int MODE>
__global__ __launch_bounds__(256) void hgemm(const float* __restrict__ Xf) {
    constexpr int MF = WM / 16;
    constexpr int NF = WN / 8;
    constexpr int NWN = BN / WN;

    __shared__ __half sA[128 * SPITCH];
    __shared__ __half sB[BN * SPITCH];

    const int t    = threadIdx.x;
    const int lane = t & 31;
    const int wid  = t >> 5;
    const int m_w  = (wid / NWN) * WM;
    const int n_w  = (wid % NWN) * WN;
    const int rowB = blockIdx.x * 128;

    __half* __restrict__ Ch = (MODE == 0) ? g_h : g_t2;
    const __half* __restrict__ Bt = (MODE == 0) ? g_w1t : g_w2t;
    const __half* __restrict__ Ah = g_a;

    float acc[MF][NF][4];
    #pragma unroll
    for (int i = 0; i < MF; ++i)
        #pragma unroll
        for (int j = 0; j < NF; ++j)
            #pragma unroll
            for (int q = 0; q < 4; ++q) acc[i][j][q] = 0.f;

    // loader indices: 2 threads per row, 16 halves each
    const int arow = t >> 1;
    const int asub = t & 1;

    #pragma unroll 1
    for (int kc = 0; kc < 4; ++kc) {
        const int k0 = kc * 32;
        // ---- load A tile: 128 rows x 32 halves
        {
            int gr = rowB + arow;
            uint4 u0, u1;
            if (MODE == 0) {
                float4 f0, f1, f2, f3;
                if (gr < NN) {
                    const float4* Xr = (const float4*)Xf + (size_t)gr * 32 + kc * 8 + asub * 4;
                    f0 = Xr[0]; f1 = Xr[1]; f2 = Xr[2]; f3 = Xr[3];
                } else {
                    f0 = f1 = f2 = f3 = make_float4(0.f, 0.f, 0.f, 0.f);
                }
                __half2 h0 = __floats2half2_rn(f0.x, f0.y), h1 = __floats2half2_rn(f0.z, f0.w);
                __half2 h2 = __floats2half2_rn(f1.x, f1.y), h3 = __floats2half2_rn(f1.z, f1.w);
                __half2 h4 = __floats2half2_rn(f2.x, f2.y), h5 = __floats2half2_rn(f2.z, f2.w);
                __half2 h6 = __floats2half2_rn(f3.x, f3.y), h7 = __floats2half2_rn(f3.z, f3.w);
                u0 = make_uint4(*(unsigned*)&h0, *(unsigned*)&h1, *(unsigned*)&h2, *(unsigned*)&h3);
                u1 = make_uint4(*(unsigned*)&h4, *(unsigned*)&h5, *(unsigned*)&h6, *(unsigned*)&h7);
            } else {
                if (gr < NN) {
                    const uint4* Ar = (const uint4*)(Ah + (size_t)gr * 128 + k0 + asub * 16);
                    u0 = Ar[0]; u1 = Ar[1];
                } else {
                    u0 = make_uint4(0u, 0u, 0u, 0u);
                    u1 = make_uint4(0u, 0u, 0u, 0u);
                }
            }
            uint4* dst = (uint4*)&sA[arow * SPITCH + asub * 16];
            dst[0] = u0; dst[1] = u1;
        }
        // ---- load B tile: BN rows x 32 halves (from pre-transposed fp16 weights)
        if (BN == 128 || t < 128) {
            int n = arow;            // for BN=64 only t<128 -> n<64
            const uint4* Br = (const uint4*)(Bt + (size_t)n * 128 + k0 + asub * 16);
            uint4* dst = (uint4*)&sB[n * SPITCH + asub * 16];
            dst[0] = Br[0]; dst[1] = Br[1];
        }
        __syncthreads();

        // ---- compute: 2 k16 steps
        #pragma unroll
        for (int ks = 0; ks < 2; ++ks) {
            unsigned af[MF][4];
            #pragma unroll
            for (int mf = 0; mf < MF; ++mf) {
                int r = m_w + mf * 16 + (lane & 15);
                int c = ks * 16 + ((lane >> 4) << 3);
                ldsm_x4(af[mf][0], af[mf][1], af[mf][2], af[mf][3],
                        smem_u32(&sA[r * SPITCH + c]));
            }
            unsigned bf[NF][2];
            #pragma unroll
            for (int nf = 0; nf < NF; ++nf) {
                int r = n_w + nf * 8 + (lane & 7);
                int c = ks * 16 + ((lane >> 3) & 1) * 8;
                ldsm_x2(bf[nf][0], bf[nf][1], smem_u32(&sB[r * SPITCH + c]));
            }
            #pragma unroll
            for (int mf = 0; mf < MF; ++mf)
                #pragma unroll
                for (int nf = 0; nf < NF; ++nf)
                    mma16816(acc[mf][nf][0], acc[mf][nf][1], acc[mf][nf][2], acc[mf][nf][3],
                             af[mf][0], af[mf][1], af[mf][2], af[mf][3],
                             bf[nf][0], bf[nf][1]);
        }
        __syncthreads();
    }

    // ---- epilogue: scale row m by dinv[m], store fp16
    #pragma unroll
    for (int mf = 0; mf < MF; ++mf) {
        int m0 = rowB + m_w + mf * 16 + (lane >> 2);
        float d0 = (m0     < NN) ? g_dinv[m0]     : 0.f;
        float d1 = (m0 + 8 < NN) ? g_dinv[m0 + 8] : 0.f;
        #pragma unroll
        for (int nf = 0; nf < NF; ++nf) {
            int n = n_w + nf * 8 + (lane & 3) * 2;
            if (m0 < NN) {
                __half2 p = __floats2half2_rn(acc[mf][nf][0] * d0, acc[mf][nf][1] * d0);
                *(__half2*)(Ch + (size_t)m0 * BN + n) = p;
            }
            if (m0 + 8 < NN) {
                __half2 p = __floats2half2_rn(acc[mf][nf][2] * d1, acc[mf][nf][3] * d1);
                *(__half2*)(Ch + (size_t)(m0 + 8) * BN + n) = p;
            }
        }
    }
}

// ---------------- gather SpMM (layer 1): 128 cols fp16, one warp per node ------
// segment of node gw = [gw? g_off[gw-1] : 0, g_off[gw])  (post-fill semantics)
__global__ void spmm1(const float* __restrict__ b1) {
    int gw   = (blockIdx.x * blockDim.x + threadIdx.x) >> 5;
    int lane = threadIdx.x & 31;
    if (gw >= NN) return;
    const __half* __restrict__ H = g_h;
    float dv = g_dinv[gw];

    uint2 h0 = *(const uint2*)(H + (size_t)gw * 128 + lane * 4);
    float2 p0 = __half22float2(*(__half2*)&h0.x);
    float2 p1 = __half22float2(*(__half2*)&h0.y);
    float a0 = p0.x, a1 = p0.y, a2 = p1.x, a3 = p1.y;

    int e  = (gw == 0) ? 0 : g_off[gw - 1];
    int e1 = g_off[gw];
    for (; e + 4 <= e1; e += 4) {
        int s0 = g_csr[e];
        int s1 = g_csr[e + 1];
        int s2 = g_csr[e + 2];
        int s3 = g_csr[e + 3];
        uint2 u0 = *(const uint2*)(H + (size_t)s0 * 128 + lane * 4);
        uint2 u1 = *(const uint2*)(H + (size_t)s1 * 128 + lane * 4);
        uint2 u2 = *(const uint2*)(H + (size_t)s2 * 128 + lane * 4);
        uint2 u3 = *(const uint2*)(H + (size_t)s3 * 128 + lane * 4);
        float2 q0 = __half22float2(*(__half2*)&u0.x), q1 = __half22float2(*(__half2*)&u0.y);
        float2 r0 = __half22float2(*(__half2*)&u1.x), r1 = __half22float2(*(__half2*)&u1.y);
        float2 w0 = __half22float2(*(__half2*)&u2.x), w1 = __half22float2(*(__half2*)&u2.y);
        float2 z0 = __half22float2(*(__half2*)&u3.x), z1 = __half22float2(*(__half2*)&u3.y);
        a0 += (q0.x + r0.x) + (w0.x + z0.x);
        a1 += (q0.y + r0.y) + (w0.y + z0.y);
        a2 += (q1.x + r1.x) + (w1.x + z1.x);
        a3 += (q1.y + r1.y) + (w1.y + z1.y);
    }
    for (; e < e1; ++e) {
        int s = g_csr[e];
        uint2 u = *(const uint2*)(H + (size_t)s * 128 + lane * 4);
        float2 q0 = __half22float2(*(__half2*)&u.x);
        float2 q1 = __half22float2(*(__half2*)&u.y);
        a0 += q0.x; a1 += q0.y; a2 += q1.x; a3 += q1.y;
    }
    float4 b = ((const float4*)b1)[lane];
    a0 = fmaxf(a0 * dv + b.x, 0.f);
    a1 = fmaxf(a1 * dv + b.y, 0.f);
    a2 = fmaxf(a2 * dv + b.z, 0.f);
    a3 = fmaxf(a3 * dv + b.w, 0.f);
    uint2 o;
    *(__half2*)&o.x = __floats2half2_rn(a0, a1);
    *(__half2*)&o.y = __floats2half2_rn(a2, a3);
    *(uint2*)(g_a + (size_t)gw * 128 + lane * 4) = o;
}

// ---------------- gather SpMM (layer 2): 64 cols fp16 in, fp32 out -------------
__global__ void spmm2(const float* __restrict__ b2, float* __restrict__ O) {
    int gw   = (blockIdx.x * blockDim.x + threadIdx.x) >> 5;
    int lane = threadIdx.x & 31;
    if (gw >= NN) return;
    const __half* __restrict__ T = g_t2;
    float dv = g_dinv[gw];

    float2 t0 = __half22float2(*(const __half2*)(T + (size_t)gw * 64 + lane * 2));
    float a0 = t0.x, a1 = t0.y;

    int e  = (gw == 0) ? 0 : g_off[gw - 1];
    int e1 = g_off[gw];
    for (; e + 4 <= e1; e += 4) {
        int s0 = g_csr[e];
        int s1 = g_csr[e + 1];
        int s2 = g_csr[e + 2];
        int s3 = g_csr[e + 3];
        float2 v0 = __half22float2(*(const __half2*)(T + (size_t)s0 * 64 + lane * 2));
        float2 v1 = __half22float2(*(const __half2*)(T + (size_t)s1 * 64 + lane * 2));
        float2 v2 = __half22float2(*(const __half2*)(T + (size_t)s2 * 64 + lane * 2));
        float2 v3 = __half22float2(*(const __half2*)(T + (size_t)s3 * 64 + lane * 2));
        a0 += (v0.x + v1.x) + (v2.x + v3.x);
        a1 += (v0.y + v1.y) + (v2.y + v3.y);
    }
    for (; e < e1; ++e) {
        int s = g_csr[e];
        float2 v = __half22float2(*(const __half2*)(T + (size_t)s * 64 + lane * 2));
        a0 += v.x;
        a1 += v.y;
    }
    float2 b = ((const float2*)b2)[lane];
    ((float2*)O)[(size_t)gw * 32 + lane] = make_float2(a0 * dv + b.x, a1 * dv + b.y);
}

// ---------------- launch: fork CSR build onto a side stream ----------------------
extern "C" void kernel_launch(void* const* d_in, const int* in_sizes, int n_in,
                              void* d_out, int out_size) {
    const float* x  = (const float*)d_in[0];
    const int*   ei = (const int*)d_in[1];     // int32 [2, E]
    const float* W1 = (const float*)d_in[2];
    const float* b1 = (const float*)d_in[3];
    const float* W2 = (const float*)d_in[4];
    const float* b2 = (const float*)d_in[5];
    float*       out = (float*)d_out;

    cudaStream_t s1;
    cudaStreamCreateWithFlags(&s1, cudaStreamNonBlocking);
    cudaEvent_t evFork, evDinv, evFill;
    cudaEventCreateWithFlags(&evFork, cudaEventDisableTiming);
    cudaEventCreateWithFlags(&evDinv, cudaEventDisableTiming);
    cudaEventCreateWithFlags(&evFill, cudaEventDisableTiming);

    const int TB = 256;

    // fork: s1 branches off the (captured) main stream
    cudaEventRecord(evFork, 0);
    cudaStreamWaitEvent(s1, evFork, 0);

    // ---- CSR build chain on s1
    k_count     <<<(EE / 4 + TB - 1) / TB, TB, 0, s1>>>(ei);
    k_scan_fused<<<SCAN_BLOCKS, SCAN_CHUNK, 0, s1>>>();
    cudaEventRecord(evDinv, s1);                 // dinv ready
    k_fill      <<<(EE / 8 + TB - 1) / TB, TB, 0, s1>>>(ei);
    cudaEventRecord(evFill, s1);                 // CSR ready

    // ---- main stream: weight prep concurrent with CSR build
    k_wprep<<<64, 256>>>(W1, W2);

    const int GB = (NN + 127) / 128;   // 782
    // hgemm1 (needs dinv only)
    cudaStreamWaitEvent(0, evDinv, 0);
    hgemm<128, 64, 32, 0><<<GB, 256>>>(x);

    // spmm1 (needs full CSR)
    cudaStreamWaitEvent(0, evFill, 0);
    spmm1<<<(NN * 32 + TB - 1) / TB, TB>>>(b1);

    hgemm<64, 32, 32, 1><<<GB, 256>>>(x /*unused*/);
    spmm2<<<(NN * 32 + TB - 1) / TB, TB>>>(b2, out);
}

// round 16
// speedup vs baseline: 1.0451x; 1.0272x over previous
#include <cuda_runtime.h>
#include <cuda_fp16.h>
#include <cstdint>
#include <stdint.h>

// Problem constants (fixed shapes)
#define NN 100000
#define EE 1600000
#define SCAN_CHUNK 1024
#define SCAN_BLOCKS ((NN + SCAN_CHUNK - 1) / SCAN_CHUNK)   // 98

// ---------------- device scratch (static globals; no runtime alloc) -------------
// g_cnt invariant: zero at entry of every kernel_launch call (zero-init BSS at
// load; k_scan_part re-zeroes after consuming each element).
__device__ int    g_cnt[NN];
__device__ int    g_off[NN + 1];
__device__ int    g_cur[NN];
__device__ int    g_part[SCAN_BLOCKS];
__device__ float  g_dinv[NN];
__device__ int    g_csr[EE];
__device__ __half g_h  [NN * 128];   // dinv * (x @ W1)      (pre-scaled rows)
__device__ __half g_a  [NN * 128];   // relu(Ahat@h+b1)
__device__ __half g_t2 [NN * 64];    // dinv * (g_a @ W2)    (pre-scaled rows)
__device__ __half g_w1t[128 * 128];  // W1^T  [n][k] fp16 (k contiguous)
__device__ __half g_w2t[64 * 128];   // W2^T  [n][k] fp16

// ---------------- weight prep: transpose + fp16 convert -------------------------
__global__ void k_wprep(const float* __restrict__ W1, const float* __restrict__ W2) {
    int i = blockIdx.x * blockDim.x + threadIdx.x;
    if (i < 128 * 128) {
        int n = i >> 7, k = i & 127;
        g_w1t[i] = __float2half(W1[k * 128 + n]);
    }
    if (i < 64 * 128) {
        int n = i >> 7, k = i & 127;
        g_w2t[i] = __float2half(W2[k * 64 + n]);
    }
}

// ---------------- degree / CSR construction ------------------------------------
// edge_index is INT32: layout [2, E] -> src = ei[e], dst = ei[E+e]
__global__ void k_count(const int* __restrict__ ei) {
    int i = blockIdx.x * blockDim.x + threadIdx.x;
    if (i < EE / 4) {
        int4 d = ((const int4*)(ei + EE))[i];
        atomicAdd(&g_cnt[d.x], 1);
        atomicAdd(&g_cnt[d.y], 1);
        atomicAdd(&g_cnt[d.z], 1);
        atomicAdd(&g_cnt[d.w], 1);
    }
}

// per-block exclusive scan into g_off; block total into g_part; dinv; re-zero cnt
__global__ void k_scan_part() {
    __shared__ int warpsum[32];
    const int tid  = threadIdx.x;
    const int lane = tid & 31;
    const int wid  = tid >> 5;
    const int i = blockIdx.x * SCAN_CHUNK + tid;

    int v = 0;
    if (i < NN) {
        v = g_cnt[i];
        g_cnt[i] = 0;                              // restore invariant for next call
        g_dinv[i] = rsqrtf((float)(v + 1));        // +1 self-loop
    }
    int s = v;
    #pragma unroll
    for (int d = 1; d < 32; d <<= 1) {
        int t = __shfl_up_sync(0xffffffffu, s, d);
        if (lane >= d) s += t;
    }
    if (lane == 31) warpsum[wid] = s;
    __syncthreads();
    if (wid == 0) {
        int ws = warpsum[lane];
        #pragma unroll
        for (int d = 1; d < 32; d <<= 1) {
            int t = __shfl_up_sync(0xffffffffu, ws, d);
            if (lane >= d) ws += t;
        }
        warpsum[lane] = ws;
    }
    __syncthreads();
    int block_excl = (wid == 0) ? 0 : warpsum[wid - 1];
    if (i < NN) g_off[i] = s + block_excl - v;
    if (tid == SCAN_CHUNK - 1) g_part[blockIdx.x] = s + block_excl;
}

// fused: compute this block's base from g_part (warp-0 scan), add, mirror to g_cur
__global__ void k_scan_add() {
    __shared__ int base_s;
    __shared__ int total_s;
    const int tid = threadIdx.x;
    const int bid = blockIdx.x;

    if (tid < 32) {
        int accBase = 0, accAll = 0;
        for (int j = tid; j < SCAN_BLOCKS; j += 32) {
            int p = g_part[j];
            accAll += p;
            if (j < bid) accBase += p;
        }
        #pragma unroll
        for (int d = 16; d; d >>= 1) {
            accBase += __shfl_down_sync(0xffffffffu, accBase, d);
            accAll  += __shfl_down_sync(0xffffffffu, accAll, d);
        }
        if (tid == 0) { base_s = accBase; total_s = accAll; }
    }
    __syncthreads();
    int i = bid * SCAN_CHUNK + tid;
    if (i < NN) {
        int o = g_off[i] + base_s;
        g_off[i] = o;
        g_cur[i] = o;
    }
    if (bid == SCAN_BLOCKS - 1 && tid == 0) g_off[NN] = total_s;
}

// 8 edges per thread (2x int4) for deeper atomic MLP
__global__ void k_fill(const int* __restrict__ ei) {
    int i = blockIdx.x * blockDim.x + threadIdx.x;
    if (i < EE / 8) {
        int4 s0 = ((const int4*)ei)[2 * i];
        int4 s1 = ((const int4*)ei)[2 * i + 1];
        int4 d0 = ((const int4*)(ei + EE))[2 * i];
        int4 d1 = ((const int4*)(ei + EE))[2 * i + 1];
        int p0 = atomicAdd(&g_cur[d0.x], 1);
        int p1 = atomicAdd(&g_cur[d0.y], 1);
        int p2 = atomicAdd(&g_cur[d0.z], 1);
        int p3 = atomicAdd(&g_cur[d0.w], 1);
        int p4 = atomicAdd(&g_cur[d1.x], 1);
        int p5 = atomicAdd(&g_cur[d1.y], 1);
        int p6 = atomicAdd(&g_cur[d1.z], 1);
        int p7 = atomicAdd(&g_cur[d1.w], 1);
        g_csr[p0] = s0.x;
        g_csr[p1] = s0.y;
        g_csr[p2] = s0.z;
        g_csr[p3] = s0.w;
        g_csr[p4] = s1.x;
        g_csr[p5] = s1.y;
        g_csr[p6] = s1.z;
        g_csr[p7] = s1.w;
    }
}

// ---------------- tensor-core helpers -------------------------------------------
__device__ __forceinline__ unsigned smem_u32(const void* p) {
    return (unsigned)__cvta_generic_to_shared(p);
}
__device__ __forceinline__ void ldsm_x4(unsigned& r0, unsigned& r1, unsigned& r2,
                                        unsigned& r3, unsigned addr) {
    asm volatile("ldmatrix.sync.aligned.m8n8.x4.shared.b16 {%0,%1,%2,%3}, [%4];"
                 : "=r"(r0), "=r"(r1), "=r"(r2), "=r"(r3) : "r"(addr));
}
__device__ __forceinline__ void ldsm_x2(unsigned& r0, unsigned& r1, unsigned addr) {
    asm volatile("ldmatrix.sync.aligned.m8n8.x2.shared.b16 {%0,%1}, [%2];"
                 : "=r"(r0), "=r"(r1) : "r"(addr));
}
__device__ __forceinline__ void mma16816(float& c0, float& c1, float& c2, float& c3,
                                         unsigned a0, unsigned a1, unsigned a2, unsigned a3,
                                         unsigned b0, unsigned b1) {
    asm volatile(
        "mma.sync.aligned.m16n8k16.row.col.f32.f16.f16.f32 "
        "{%0,%1,%2,%3}, {%4,%5,%6,%7}, {%8,%9}, {%0,%1,%2,%3};"
        : "+f"(c0), "+f"(c1), "+f"(c2), "+f"(c3)
        : "r"(a0), "r"(a1), "r"(a2), "r"(a3), "r"(b0), "r"(b1));
}

// ---------------- HMMA GEMM: C[m] = dinv[m] * (A[m] @ W), fp16 out ---------------
// Block tile 128 x BN, BK=32, 256 threads (8 warps).
// MODE 0: A = x (fp32 arg) -> g_h    (BN=128, WM=64, WN=32)
// MODE 1: A = g_a (fp16)   -> g_t2   (BN=64,  WM=32, WN=32)
#define SPITCH 40   // halves per smem row (conflict-free under ldmatrix)

template <int BN, int WM, int WN, int MODE>
__global__ __launch_bounds__(256) void hgemm(const float* __restrict__ Xf) {
    constexpr int MF = WM / 16;
    constexpr int NF = WN / 8;
    constexpr int NWN = BN / WN;

    __shared__ __half sA[128 * SPITCH];
    __shared__ __half sB[BN * SPITCH];

    const int t    = threadIdx.x;
    const int lane = t & 31;
    const int wid  = t >> 5;
    const int m_w  = (wid / NWN) * WM;
    const int n_w  = (wid % NWN) * WN;
    const int rowB = blockIdx.x * 128;

    __half* __restrict__ Ch = (MODE == 0) ? g_h : g_t2;
    const __half* __restrict__ Bt = (MODE == 0) ? g_w1t : g_w2t;
    const __half* __restrict__ Ah = g_a;

    float acc[MF][NF][4];
    #pragma unroll
    for (int i = 0; i < MF; ++i)
        #pragma unroll
        for (int j = 0; j < NF; ++j)
            #pragma unroll
            for (int q = 0; q < 4; ++q) acc[i][j][q] = 0.f;

    // loader indices: 2 threads per row, 16 halves each
    const int arow = t >> 1;
    const int asub = t & 1;

    #pragma unroll 1
    for (int kc = 0; kc < 4; ++kc) {
        const int k0 = kc * 32;
        // ---- load A tile: 128 rows x 32 halves
        {
            int gr = rowB + arow;
            uint4 u0, u1;
            if (MODE == 0) {
                float4 f0, f1, f2, f3;
                if (gr < NN) {
                    const float4* Xr = (const float4*)Xf + (size_t)gr * 32 + kc * 8 + asub * 4;
                    f0 = Xr[0]; f1 = Xr[1]; f2 = Xr[2]; f3 = Xr[3];
                } else {
                    f0 = f1 = f2 = f3 = make_float4(0.f, 0.f, 0.f, 0.f);
                }
                __half2 h0 = __floats2half2_rn(f0.x, f0.y), h1 = __floats2half2_rn(f0.z, f0.w);
                __half2 h2 = __floats2half2_rn(f1.x, f1.y), h3 = __floats2half2_rn(f1.z, f1.w);
                __half2 h4 = __floats2half2_rn(f2.x, f2.y), h5 = __floats2half2_rn(f2.z, f2.w);
                __half2 h6 = __floats2half2_rn(f3.x, f3.y), h7 = __floats2half2_rn(f3.z, f3.w);
                u0 = make_uint4(*(unsigned*)&h0, *(unsigned*)&h1, *(unsigned*)&h2, *(unsigned*)&h3);
                u1 = make_uint4(*(unsigned*)&h4, *(unsigned*)&h5, *(unsigned*)&h6, *(unsigned*)&h7);
            } else {
                if (gr < NN) {
                    const uint4* Ar = (const uint4*)(Ah + (size_t)gr * 128 + k0 + asub * 16);
                    u0 = Ar[0]; u1 = Ar[1];
                } else {
                    u0 = make_uint4(0u, 0u, 0u, 0u);
                    u1 = make_uint4(0u, 0u, 0u, 0u);
                }
            }
            uint4* dst = (uint4*)&sA[arow * SPITCH + asub * 16];
            dst[0] = u0; dst[1] = u1;
        }
        // ---- load B tile: BN rows x 32 halves (from pre-transposed fp16 weights)
        if (BN == 128 || t < 128) {
            int n = arow;            // for BN=64 only t<128 -> n<64
            const uint4* Br = (const uint4*)(Bt + (size_t)n * 128 + k0 + asub * 16);
            uint4* dst = (uint4*)&sB[n * SPITCH + asub * 16];
            dst[0] = Br[0]; dst[1] = Br[1];
        }
        __syncthreads();

        // ---- compute: 2 k16 steps
        #pragma unroll
        for (int ks = 0; ks < 2; ++ks) {
            unsigned af[MF][4];
            #pragma unroll
            for (int mf = 0; mf < MF; ++mf) {
                int r = m_w + mf * 16 + (lane & 15);
                int c = ks * 16 + ((lane >> 4) << 3);
                ldsm_x4(af[mf][0], af[mf][1], af[mf][2], af[mf][3],
                        smem_u32(&sA[r * SPITCH + c]));
            }
            unsigned bf[NF][2];
            #pragma unroll
            for (int nf = 0; nf < NF; ++nf) {
                int r = n_w + nf * 8 + (lane & 7);
                int c = ks * 16 + ((lane >> 3) & 1) * 8;
                ldsm_x2(bf[nf][0], bf[nf][1], smem_u32(&sB[r * SPITCH + c]));
            }
            #pragma unroll
            for (int mf = 0; mf < MF; ++mf)
                #pragma unroll
                for (int nf = 0; nf < NF; ++nf)
                    mma16816(acc[mf][nf][0], acc[mf][nf][1], acc[mf][nf][2], acc[mf][nf][3],
                             af[mf][0], af[mf][1], af[mf][2], af[mf][3],
                             bf[nf][0], bf[nf][1]);
        }
        __syncthreads();
    }

    // ---- epilogue: scale row m by dinv[m], store fp16
    #pragma unroll
    for (int mf = 0; mf < MF; ++mf) {
        int m0 = rowB + m_w + mf * 16 + (lane >> 2);
        float d0 = (m0     < NN) ? g_dinv[m0]     : 0.f;
        float d1 = (m0 + 8 < NN) ? g_dinv[m0 + 8] : 0.f;
        #pragma unroll
        for (int nf = 0; nf < NF; ++nf) {
            int n = n_w + nf * 8 + (lane & 3) * 2;
            if (m0 < NN) {
                __half2 p = __floats2half2_rn(acc[mf][nf][0] * d0, acc[mf][nf][1] * d0);
                *(__half2*)(Ch + (size_t)m0 * BN + n) = p;
            }
            if (m0 + 8 < NN) {
                __half2 p = __floats2half2_rn(acc[mf][nf][2] * d1, acc[mf][nf][3] * d1);
                *(__half2*)(Ch + (size_t)(m0 + 8) * BN + n) = p;
            }
        }
    }
}

// ---------------- gather SpMM (layer 1): 128 cols fp16, one warp per node ------
// g_h rows are pre-scaled by dinv[src]; result = relu(dinv[d]*(sum + self) + b1).
// 8-way unrolled edge loop (16 gathers in flight per warp).
__global__ void spmm1(const float* __restrict__ b1) {
    int gw   = (blockIdx.x * blockDim.x + threadIdx.x) >> 5;
    int lane = threadIdx.x & 31;
    if (gw >= NN) return;
    const __half* __restrict__ H = g_h;
    float dv = g_dinv[gw];

    uint2 h0 = *(const uint2*)(H + (size_t)gw * 128 + lane * 4);
    float2 p0 = __half22float2(*(__half2*)&h0.x);
    float2 p1 = __half22float2(*(__half2*)&h0.y);
    float a0 = p0.x, a1 = p0.y, a2 = p1.x, a3 = p1.y;

    int e = g_off[gw], e1 = g_off[gw + 1];
    for (; e + 8 <= e1; e += 8) {
        int sx[8];
        #pragma unroll
        for (int j = 0; j < 8; ++j) sx[j] = g_csr[e + j];
        uint2 u[8];
        #pragma unroll
        for (int j = 0; j < 8; ++j)
            u[j] = *(const uint2*)(H + (size_t)sx[j] * 128 + lane * 4);
        #pragma unroll
        for (int j = 0; j < 8; ++j) {
            float2 q0 = __half22float2(*(__half2*)&u[j].x);
            float2 q1 = __half22float2(*(__half2*)&u[j].y);
            a0 += q0.x; a1 += q0.y; a2 += q1.x; a3 += q1.y;
        }
    }
    for (; e < e1; ++e) {
        int s = g_csr[e];
        uint2 u = *(const uint2*)(H + (size_t)s * 128 + lane * 4);
        float2 q0 = __half22float2(*(__half2*)&u.x);
        float2 q1 = __half22float2(*(__half2*)&u.y);
        a0 += q0.x; a1 += q0.y; a2 += q1.x; a3 += q1.y;
    }
    float4 b = ((const float4*)b1)[lane];
    a0 = fmaxf(a0 * dv + b.x, 0.f);
    a1 = fmaxf(a1 * dv + b.y, 0.f);
    a2 = fmaxf(a2 * dv + b.z, 0.f);
    a3 = fmaxf(a3 * dv + b.w, 0.f);
    uint2 o;
    *(__half2*)&o.x = __floats2half2_rn(a0, a1);
    *(__half2*)&o.y = __floats2half2_rn(a2, a3);
    *(uint2*)(g_a + (size_t)gw * 128 + lane * 4) = o;
}

// ---------------- gather SpMM (layer 2): 64 cols fp16 in, fp32 out -------------
// g_t2 rows pre-scaled by dinv[src]; out = dinv[d]*(sum + self) + b2. 8-way unroll.
__global__ void spmm2(const float* __restrict__ b2, float* __restrict__ O) {
    int gw   = (blockIdx.x * blockDim.x + threadIdx.x) >> 5;
    int lane = threadIdx.x & 31;
    if (gw >= NN) return;
    const __half* __restrict__ T = g_t2;
    float dv = g_dinv[gw];

    float2 t0 = __half22float2(*(const __half2*)(T + (size_t)gw * 64 + lane * 2));
    float a0 = t0.x, a1 = t0.y;

    int e = g_off[gw], e1 = g_off[gw + 1];
    for (; e + 8 <= e1; e += 8) {
        int sx[8];
        #pragma unroll
        for (int j = 0; j < 8; ++j) sx[j] = g_csr[e + j];
        unsigned u[8];
        #pragma unroll
        for (int j = 0; j < 8; ++j)
            u[j] = *(const unsigned*)(T + (size_t)sx[j] * 64 + lane * 2);
        #pragma unroll
        for (int j = 0; j < 8; ++j) {
            float2 v = __half22float2(*(__half2*)&u[j]);
            a0 += v.x; a1 += v.y;
        }
    }
    for (; e < e1; ++e) {
        int s = g_csr[e];
        float2 v = __half22float2(*(const __half2*)(T + (size_t)s * 64 + lane * 2));
        a0 += v.x;
        a1 += v.y;
    }
    float2 b = ((const float2*)b2)[lane];
    ((float2*)O)[(size_t)gw * 32 + lane] = make_float2(a0 * dv + b.x, a1 * dv + b.y);
}

// ---------------- launch: fork CSR build onto a side stream ----------------------
extern "C" void kernel_launch(void* const* d_in, const int* in_sizes, int n_in,
                              void* d_out, int out_size) {
    const float* x  = (const float*)d_in[0];
    const int*   ei = (const int*)d_in[1];     // int32 [2, E]
    const float* W1 = (const float*)d_in[2];
    const float* b1 = (const float*)d_in[3];
    const float* W2 = (const float*)d_in[4];
    const float* b2 = (const float*)d_in[5];
    float*       out = (float*)d_out;

    cudaStream_t s1;
    cudaStreamCreateWithFlags(&s1, cudaStreamNonBlocking);
    cudaEvent_t evFork, evDinv, evFill;
    cudaEventCreateWithFlags(&evFork, cudaEventDisableTiming);
    cudaEventCreateWithFlags(&evDinv, cudaEventDisableTiming);
    cudaEventCreateWithFlags(&evFill, cudaEventDisableTiming);

    const int TB = 256;

    // fork: s1 branches off the (captured) main stream
    cudaEventRecord(evFork, 0);
    cudaStreamWaitEvent(s1, evFork, 0);

    // ---- CSR build chain on s1
    k_count    <<<(EE / 4 + TB - 1) / TB, TB, 0, s1>>>(ei);
    k_scan_part<<<SCAN_BLOCKS, SCAN_CHUNK, 0, s1>>>();
    cudaEventRecord(evDinv, s1);                 // dinv ready
    k_scan_add <<<SCAN_BLOCKS, SCAN_CHUNK, 0, s1>>>();
    k_fill     <<<(EE / 8 + TB - 1) / TB, TB, 0, s1>>>(ei);
    cudaEventRecord(evFill, s1);                 // CSR ready

    // ---- main stream: weight prep concurrent with CSR build
    k_wprep<<<64, 256>>>(W1, W2);

    const int GB = (NN + 127) / 128;   // 782
    // hgemm1 (needs dinv only)
    cudaStreamWaitEvent(0, evDinv, 0);
    hgemm<128, 64, 32, 0><<<GB, 256>>>(x);

    // spmm1 (needs full CSR)
    cudaStreamWaitEvent(0, evFill, 0);
    spmm1<<<(NN * 32 + TB - 1) / TB, TB>>>(b1);

    hgemm<64, 32, 32, 1><<<GB, 256>>>(x /*unused*/);
    spmm2<<<(NN * 32 + TB - 1) / TB, TB>>>(b2, out);
}

// round 17
// speedup vs baseline: 1.0538x; 1.0083x over previous
#include <cuda_runtime.h>
#include <cuda_fp16.h>
#include <cstdint>
#include <stdint.h>

// Problem constants (fixed shapes)
#define NN 100000
#define EE 1600000
#define SCAN_CHUNK 1024
#define SCAN_BLOCKS ((NN + SCAN_CHUNK - 1) / SCAN_CHUNK)   // 98

// ---------------- device scratch (static globals; no runtime alloc) -------------
// g_cnt invariant: zero at entry of every kernel_launch call (zero-init BSS at
// load; k_scan_part re-zeroes after consuming each element).
__device__ int    g_cnt[NN];
__device__ int    g_off[NN + 1];
__device__ int    g_part[SCAN_BLOCKS];
__device__ int    g_rank[EE];        // per-edge rank within its dst bucket
__device__ float  g_dinv[NN];
__device__ int    g_csr[EE];
__device__ __half g_h  [NN * 128];   // dinv * (x @ W1)      (pre-scaled rows)
__device__ __half g_a  [NN * 128];   // relu(Ahat@h+b1)
__device__ __half g_t2 [NN * 64];    // dinv * (g_a @ W2)    (pre-scaled rows)
__device__ __half g_w1t[128 * 128];  // W1^T  [n][k] fp16 (k contiguous)
__device__ __half g_w2t[64 * 128];   // W2^T  [n][k] fp16

// ---------------- weight prep: transpose + fp16 convert -------------------------
__global__ void k_wprep(const float* __restrict__ W1, const float* __restrict__ W2) {
    int i = blockIdx.x * blockDim.x + threadIdx.x;
    if (i < 128 * 128) {
        int n = i >> 7, k = i & 127;
        g_w1t[i] = __float2half(W1[k * 128 + n]);
    }
    if (i < 64 * 128) {
        int n = i >> 7, k = i & 127;
        g_w2t[i] = __float2half(W2[k * 64 + n]);
    }
}

// ---------------- degree / CSR construction ------------------------------------
// edge_index is INT32: layout [2, E] -> src = ei[e], dst = ei[E+e]
// count ALSO records each edge's rank within its dst bucket (the atomic return).
__global__ void k_count(const int* __restrict__ ei) {
    int i = blockIdx.x * blockDim.x + threadIdx.x;
    if (i < EE / 4) {
        int4 d = ((const int4*)(ei + EE))[i];
        int4 r;
        r.x = atomicAdd(&g_cnt[d.x], 1);
        r.y = atomicAdd(&g_cnt[d.y], 1);
        r.z = atomicAdd(&g_cnt[d.z], 1);
        r.w = atomicAdd(&g_cnt[d.w], 1);
        ((int4*)g_rank)[i] = r;
    }
}

// per-block exclusive scan into g_off; block total into g_part; dinv; re-zero cnt
__global__ void k_scan_part() {
    __shared__ int warpsum[32];
    const int tid  = threadIdx.x;
    const int lane = tid & 31;
    const int wid  = tid >> 5;
    const int i = blockIdx.x * SCAN_CHUNK + tid;

    int v = 0;
    if (i < NN) {
        v = g_cnt[i];
        g_cnt[i] = 0;                              // restore invariant for next call
        g_dinv[i] = rsqrtf((float)(v + 1));        // +1 self-loop
    }
    int s = v;
    #pragma unroll
    for (int d = 1; d < 32; d <<= 1) {
        int t = __shfl_up_sync(0xffffffffu, s, d);
        if (lane >= d) s += t;
    }
    if (lane == 31) warpsum[wid] = s;
    __syncthreads();
    if (wid == 0) {
        int ws = warpsum[lane];
        #pragma unroll
        for (int d = 1; d < 32; d <<= 1) {
            int t = __shfl_up_sync(0xffffffffu, ws, d);
            if (lane >= d) ws += t;
        }
        warpsum[lane] = ws;
    }
    __syncthreads();
    int block_excl = (wid == 0) ? 0 : warpsum[wid - 1];
    if (i < NN) g_off[i] = s + block_excl - v;
    if (tid == SCAN_CHUNK - 1) g_part[blockIdx.x] = s + block_excl;
}

// fused: compute this block's base from g_part (warp-0 reduce), add to g_off
__global__ void k_scan_add() {
    __shared__ int base_s;
    __shared__ int total_s;
    const int tid = threadIdx.x;
    const int bid = blockIdx.x;

    if (tid < 32) {
        int accBase = 0, accAll = 0;
        for (int j = tid; j < SCAN_BLOCKS; j += 32) {
            int p = g_part[j];
            accAll += p;
            if (j < bid) accBase += p;
        }
        #pragma unroll
        for (int d = 16; d; d >>= 1) {
            accBase += __shfl_down_sync(0xffffffffu, accBase, d);
            accAll  += __shfl_down_sync(0xffffffffu, accAll, d);
        }
        if (tid == 0) { base_s = accBase; total_s = accAll; }
    }
    __syncthreads();
    int i = bid * SCAN_CHUNK + tid;
    if (i < NN) g_off[i] += base_s;
    if (bid == SCAN_BLOCKS - 1 && tid == 0) g_off[NN] = total_s;
}

// ATOMIC-FREE fill: position = off[dst] + rank[edge]; pure loads + stores.
__global__ void k_fill(const int* __restrict__ ei) {
    int i = blockIdx.x * blockDim.x + threadIdx.x;
    if (i < EE / 4) {
        int4 s = ((const int4*)ei)[i];
        int4 d = ((const int4*)(ei + EE))[i];
        int4 r = ((const int4*)g_rank)[i];
        g_csr[g_off[d.x] + r.x] = s.x;
        g_csr[g_off[d.y] + r.y] = s.y;
        g_csr[g_off[d.z] + r.z] = s.z;
        g_csr[g_off[d.w] + r.w] = s.w;
    }
}

// ---------------- tensor-core helpers -------------------------------------------
__device__ __forceinline__ unsigned smem_u32(const void* p) {
    return (unsigned)__cvta_generic_to_shared(p);
}
__device__ __forceinline__ void ldsm_x4(unsigned& r0, unsigned& r1, unsigned& r2,
                                        unsigned& r3, unsigned addr) {
    asm volatile("ldmatrix.sync.aligned.m8n8.x4.shared.b16 {%0,%1,%2,%3}, [%4];"
                 : "=r"(r0), "=r"(r1), "=r"(r2), "=r"(r3) : "r"(addr));
}
__device__ __forceinline__ void ldsm_x2(unsigned& r0, unsigned& r1, unsigned addr) {
    asm volatile("ldmatrix.sync.aligned.m8n8.x2.shared.b16 {%0,%1}, [%2];"
                 : "=r"(r0), "=r"(r1) : "r"(addr));
}
__device__ __forceinline__ void mma16816(float& c0, float& c1, float& c2, float& c3,
                                         unsigned a0, unsigned a1, unsigned a2, unsigned a3,
                                         unsigned b0, unsigned b1) {
    asm volatile(
        "mma.sync.aligned.m16n8k16.row.col.f32.f16.f16.f32 "
        "{%0,%1,%2,%3}, {%4,%5,%6,%7}, {%8,%9}, {%0,%1,%2,%3};"
        : "+f"(c0), "+f"(c1), "+f"(c2), "+f"(c3)
        : "r"(a0), "r"(a1), "r"(a2), "r"(a3), "r"(b0), "r"(b1));
}

// ---------------- HMMA GEMM: C[m] = dinv[m] * (A[m] @ W), fp16 out ---------------
// Block tile 128 x BN, BK=32, 256 threads (8 warps).
// MODE 0: A = x (fp32 arg) -> g_h    (BN=128, WM=64, WN=32)
// MODE 1: A = g_a (fp16)   -> g_t2   (BN=64,  WM=32, WN=32)
#define SPITCH 40   // halves per smem row (conflict-free under ldmatrix)

template <int BN, int WM, int WN, int MODE>
__global__ __launch_bounds__(256) void hgemm(const float* __restrict__ Xf) {
    constexpr int MF = WM / 16;
    constexpr int NF = WN / 8;
    constexpr int NWN = BN / WN;

    __shared__ __half sA[128 * SPITCH];
    __shared__ __half sB[BN * SPITCH];

    const int t    = threadIdx.x;
    const int lane = t & 31;
    const int wid  = t >> 5;
    const int m_w  = (wid / NWN) * WM;
    const int n_w  = (wid % NWN) * WN;
    const int rowB = blockIdx.x * 128;

    __half* __restrict__ Ch = (MODE == 0) ? g_h : g_t2;
    const __half* __restrict__ Bt = (MODE == 0) ? g_w1t : g_w2t;
    const __half* __restrict__ Ah = g_a;

    float acc[MF][NF][4];
    #pragma unroll
    for (int i = 0; i < MF; ++i)
        #pragma unroll
        for (int j = 0; j < NF; ++j)
            #pragma unroll
            for (int q = 0; q < 4; ++q) acc[i][j][q] = 0.f;

    // loader indices: 2 threads per row, 16 halves each
    const int arow = t >> 1;
    const int asub = t & 1;

    #pragma unroll 1
    for (int kc = 0; kc < 4; ++kc) {
        const int k0 = kc * 32;
        // ---- load A tile: 128 rows x 32 halves
        {
            int gr = rowB + arow;
            uint4 u0, u1;
            if (MODE == 0) {
                float4 f0, f1, f2, f3;
                if (gr < NN) {
                    const float4* Xr = (const float4*)Xf + (size_t)gr * 32 + kc * 8 + asub * 4;
                    f0 = Xr[0]; f1 = Xr[1]; f2 = Xr[2]; f3 = Xr[3];
                } else {
                    f0 = f1 = f2 = f3 = make_float4(0.f, 0.f, 0.f, 0.f);
                }
                __half2 h0 = __floats2half2_rn(f0.x, f0.y), h1 = __floats2half2_rn(f0.z, f0.w);
                __half2 h2 = __floats2half2_rn(f1.x, f1.y), h3 = __floats2half2_rn(f1.z, f1.w);
                __half2 h4 = __floats2half2_rn(f2.x, f2.y), h5 = __floats2half2_rn(f2.z, f2.w);
                __half2 h6 = __floats2half2_rn(f3.x, f3.y), h7 = __floats2half2_rn(f3.z, f3.w);
                u0 = make_uint4(*(unsigned*)&h0, *(unsigned*)&h1, *(unsigned*)&h2, *(unsigned*)&h3);
                u1 = make_uint4(*(unsigned*)&h4, *(unsigned*)&h5, *(unsigned*)&h6, *(unsigned*)&h7);
            } else {
                if (gr < NN) {
                    const uint4* Ar = (const uint4*)(Ah + (size_t)gr * 128 + k0 + asub * 16);
                    u0 = Ar[0]; u1 = Ar[1];
                } else {
                    u0 = make_uint4(0u, 0u, 0u, 0u);
                    u1 = make_uint4(0u, 0u, 0u, 0u);
                }
            }
            uint4* dst = (uint4*)&sA[arow * SPITCH + asub * 16];
            dst[0] = u0; dst[1] = u1;
        }
        // ---- load B tile: BN rows x 32 halves (from pre-transposed fp16 weights)
        if (BN == 128 || t < 128) {
            int n = arow;            // for BN=64 only t<128 -> n<64
            const uint4* Br = (const uint4*)(Bt + (size_t)n * 128 + k0 + asub * 16);
            uint4* dst = (uint4*)&sB[n * SPITCH + asub * 16];
            dst[0] = Br[0]; dst[1] = Br[1];
        }
        __syncthreads();

        // ---- compute: 2 k16 steps
        #pragma unroll
        for (int ks = 0; ks < 2; ++ks) {
            unsigned af[MF][4];
            #pragma unroll
            for (int mf = 0; mf < MF; ++mf) {
                int r = m_w + mf * 16 + (lane & 15);
                int c = ks * 16 + ((lane >> 4) << 3);
                ldsm_x4(af[mf][0], af[mf][1], af[mf][2], af[mf][3],
                        smem_u32(&sA[r * SPITCH + c]));
            }
            unsigned bf[NF][2];
            #pragma unroll
            for (int nf = 0; nf < NF; ++nf) {
                int r = n_w + nf * 8 + (lane & 7);
                int c = ks * 16 + ((lane >> 3) & 1) * 8;
                ldsm_x2(bf[nf][0], bf[nf][1], smem_u32(&sB[r * SPITCH + c]));
            }
            #pragma unroll
            for (int mf = 0; mf < MF; ++mf)
                #pragma unroll
                for (int nf = 0; nf < NF; ++nf)
                    mma16816(acc[mf][nf][0], acc[mf][nf][1], acc[mf][nf][2], acc[mf][nf][3],
                             af[mf][0], af[mf][1], af[mf][2], af[mf][3],
                             bf[nf][0], bf[nf][1]);
        }
        __syncthreads();
    }

    // ---- epilogue: scale row m by dinv[m], store fp16
    #pragma unroll
    for (int mf = 0; mf < MF; ++mf) {
        int m0 = rowB + m_w + mf * 16 + (lane >> 2);
        float d0 = (m0     < NN) ? g_dinv[m0]     : 0.f;
        float d1 = (m0 + 8 < NN) ? g_dinv[m0 + 8] : 0.f;
        #pragma unroll
        for (int nf = 0; nf < NF; ++nf) {
            int n = n_w + nf * 8 + (lane & 3) * 2;
            if (m0 < NN) {
                __half2 p = __floats2half2_rn(acc[mf][nf][0] * d0, acc[mf][nf][1] * d0);
                *(__half2*)(Ch + (size_t)m0 * BN + n) = p;
            }
            if (m0 + 8 < NN) {
                __half2 p = __floats2half2_rn(acc[mf][nf][2] * d1, acc[mf][nf][3] * d1);
                *(__half2*)(Ch + (size_t)(m0 + 8) * BN + n) = p;
            }
        }
    }
}

// ---------------- gather SpMM (layer 1): 128 cols fp16, one warp per node ------
// g_h rows are pre-scaled by dinv[src]; result = relu(dinv[d]*(sum + self) + b1).
__global__ void spmm1(const float* __restrict__ b1) {
    int gw   = (blockIdx.x * blockDim.x + threadIdx.x) >> 5;
    int lane = threadIdx.x & 31;
    if (gw >= NN) return;
    const __half* __restrict__ H = g_h;
    float dv = g_dinv[gw];

    uint2 h0 = *(const uint2*)(H + (size_t)gw * 128 + lane * 4);
    float2 p0 = __half22float2(*(__half2*)&h0.x);
    float2 p1 = __half22float2(*(__half2*)&h0.y);
    float a0 = p0.x, a1 = p0.y, a2 = p1.x, a3 = p1.y;

    int e = g_off[gw], e1 = g_off[gw + 1];
    for (; e + 4 <= e1; e += 4) {
        int s0 = g_csr[e];
        int s1 = g_csr[e + 1];
        int s2 = g_csr[e + 2];
        int s3 = g_csr[e + 3];
        uint2 u0 = *(const uint2*)(H + (size_t)s0 * 128 + lane * 4);
        uint2 u1 = *(const uint2*)(H + (size_t)s1 * 128 + lane * 4);
        uint2 u2 = *(const uint2*)(H + (size_t)s2 * 128 + lane * 4);
        uint2 u3 = *(const uint2*)(H + (size_t)s3 * 128 + lane * 4);
        float2 q0 = __half22float2(*(__half2*)&u0.x), q1 = __half22float2(*(__half2*)&u0.y);
        float2 r0 = __half22float2(*(__half2*)&u1.x), r1 = __half22float2(*(__half2*)&u1.y);
        float2 w0 = __half22float2(*(__half2*)&u2.x), w1 = __half22float2(*(__half2*)&u2.y);
        float2 z0 = __half22float2(*(__half2*)&u3.x), z1 = __half22float2(*(__half2*)&u3.y);
        a0 += (q0.x + r0.x) + (w0.x + z0.x);
        a1 += (q0.y + r0.y) + (w0.y + z0.y);
        a2 += (q1.x + r1.x) + (w1.x + z1.x);
        a3 += (q1.y + r1.y) + (w1.y + z1.y);
    }
    for (; e < e1; ++e) {
        int s = g_csr[e];
        uint2 u = *(const uint2*)(H + (size_t)s * 128 + lane * 4);
        float2 q0 = __half22float2(*(__half2*)&u.x);
        float2 q1 = __half22float2(*(__half2*)&u.y);
        a0 += q0.x; a1 += q0.y; a2 += q1.x; a3 += q1.y;
    }
    float4 b = ((const float4*)b1)[lane];
    a0 = fmaxf(a0 * dv + b.x, 0.f);
    a1 = fmaxf(a1 * dv + b.y, 0.f);
    a2 = fmaxf(a2 * dv + b.z, 0.f);
    a3 = fmaxf(a3 * dv + b.w, 0.f);
    uint2 o;
    *(__half2*)&o.x = __floats2half2_rn(a0, a1);
    *(__half2*)&o.y = __floats2half2_rn(a2, a3);
    *(uint2*)(g_a + (size_t)gw * 128 + lane * 4) = o;
}

// ---------------- gather SpMM (layer 2): 64 cols fp16 in, fp32 out -------------
// g_t2 rows pre-scaled by dinv[src]; out = dinv[d]*(sum + self) + b2.
__global__ void spmm2(const float* __restrict__ b2, float* __restrict__ O) {
    int gw   = (blockIdx.x * blockDim.x + threadIdx.x) >> 5;
    int lane = threadIdx.x & 31;
    if (gw >= NN) return;
    const __half* __restrict__ T = g_t2;
    float dv = g_dinv[gw];

    float2 t0 = __half22float2(*(const __half2*)(T + (size_t)gw * 64 + lane * 2));
    float a0 = t0.x, a1 = t0.y;

    int e = g_off[gw], e1 = g_off[gw + 1];
    for (; e + 4 <= e1; e += 4) {
        int s0 = g_csr[e];
        int s1 = g_csr[e + 1];
        int s2 = g_csr[e + 2];
        int s3 = g_csr[e + 3];
        float2 v0 = __half22float2(*(const __half2*)(T + (size_t)s0 * 64 + lane * 2));
        float2 v1 = __half22float2(*(const __half2*)(T + (size_t)s1 * 64 + lane * 2));
        float2 v2 = __half22float2(*(const __half2*)(T + (size_t)s2 * 64 + lane * 2));
        float2 v3 = __half22float2(*(const __half2*)(T + (size_t)s3 * 64 + lane * 2));
        a0 += (v0.x + v1.x) + (v2.x + v3.x);
        a1 += (v0.y + v1.y) + (v2.y + v3.y);
    }
    for (; e < e1; ++e) {
        int s = g_csr[e];
        float2 v = __half22float2(*(const __half2*)(T + (size_t)s * 64 + lane * 2));
        a0 += v.x;
        a1 += v.y;
    }
    float2 b = ((const float2*)b2)[lane];
    ((float2*)O)[(size_t)gw * 32 + lane] = make_float2(a0 * dv + b.x, a1 * dv + b.y);
}

// ---------------- launch: fork CSR build onto a side stream ----------------------
extern "C" void kernel_launch(void* const* d_in, const int* in_sizes, int n_in,
                              void* d_out, int out_size) {
    const float* x  = (const float*)d_in[0];
    const int*   ei = (const int*)d_in[1];     // int32 [2, E]
    const float* W1 = (const float*)d_in[2];
    const float* b1 = (const float*)d_in[3];
    const float* W2 = (const float*)d_in[4];
    const float* b2 = (const float*)d_in[5];
    float*       out = (float*)d_out;

    cudaStream_t s1;
    cudaStreamCreateWithFlags(&s1, cudaStreamNonBlocking);
    cudaEvent_t evFork, evDinv, evFill;
    cudaEventCreateWithFlags(&evFork, cudaEventDisableTiming);
    cudaEventCreateWithFlags(&evDinv, cudaEventDisableTiming);
    cudaEventCreateWithFlags(&evFill, cudaEventDisableTiming);

    const int TB = 256;

    // fork: s1 branches off the (captured) main stream
    cudaEventRecord(evFork, 0);
    cudaStreamWaitEvent(s1, evFork, 0);

    // ---- CSR build chain on s1
    k_count    <<<(EE / 4 + TB - 1) / TB, TB, 0, s1>>>(ei);
    k_scan_part<<<SCAN_BLOCKS, SCAN_CHUNK, 0, s1>>>();
    cudaEventRecord(evDinv, s1);                 // dinv ready
    k_scan_add <<<SCAN_BLOCKS, SCAN_CHUNK, 0, s1>>>();
    k_fill     <<<(EE / 4 + TB - 1) / TB, TB, 0, s1>>>(ei);
    cudaEventRecord(evFill, s1);                 // CSR ready

    // ---- main stream: weight prep concurrent with CSR build
    k_wprep<<<64, 256>>>(W1, W2);

    const int GB = (NN + 127) / 128;   // 782
    // hgemm1 (needs dinv only)
    cudaStreamWaitEvent(0, evDinv, 0);
    hgemm<128, 64, 32, 0><<<GB, 256>>>(x);

    // spmm1 (needs full CSR)
    cudaStreamWaitEvent(0, evFill, 0);
    spmm1<<<(NN * 32 + TB - 1) / TB, TB>>>(b1);

    hgemm<64, 32, 32, 1><<<GB, 256>>>(x /*unused*/);
    spmm2<<<(NN * 32 + TB - 1) / TB, TB>>>(b2, out);
}